// round 14
// baseline (speedup 1.0000x reference)
#include <cuda_runtime.h>

// Cross product along dim=1 of (16, 3, 1024, 1024) fp32.
// FINAL champion (5 verification runs): one float4-triple per thread, plain
// LDG.128/STG.128, full 2D grid, TPB=512.
// kernel 80.5-82.5us @ 6.8-6.93 TB/s (86-87.5% dram_active) — HBM controller
// ceiling for a 2:1 read/write mix on 576 MiB algorithmic-minimum traffic.
//
// Mapped & falsified: TPB 256 (tied) / 1024 (worse, occ 39.5%); VPT=2
// (83.4us); persistent grid (93.6us, serialized MLP); __ldcs/__stcs
// (neutral/negative). TMA/cp.async path-equivalent under the ~6300 B/cyc
// LTS cap. Stores are full-line (no RFO traffic). Converged.

static constexpr int CH_ELEMS  = 1024 * 1024;      // elements per channel plane
static constexpr int CH_VEC    = CH_ELEMS / 4;     // float4 vecs per channel plane
static constexpr int NBATCH    = 16;
static constexpr int TPB       = 512;

__global__ __launch_bounds__(TPB) void cross_kernel(
    const float4* __restrict__ A,
    const float4* __restrict__ B,
    float4* __restrict__ O)
{
    const int s = blockIdx.x * TPB + threadIdx.x;       // spatial vec index [0, CH_VEC)
    const int b = blockIdx.y;                           // batch
    const long base = (long)b * (3L * CH_VEC) + s;

    const float4 a0 = A[base];
    const float4 a1 = A[base + CH_VEC];
    const float4 a2 = A[base + 2 * CH_VEC];
    const float4 b0 = B[base];
    const float4 b1 = B[base + CH_VEC];
    const float4 b2 = B[base + 2 * CH_VEC];

    float4 c0, c1, c2;
    c0.x = fmaf(a1.x, b2.x, -a2.x * b1.x);
    c0.y = fmaf(a1.y, b2.y, -a2.y * b1.y);
    c0.z = fmaf(a1.z, b2.z, -a2.z * b1.z);
    c0.w = fmaf(a1.w, b2.w, -a2.w * b1.w);

    c1.x = fmaf(a2.x, b0.x, -a0.x * b2.x);
    c1.y = fmaf(a2.y, b0.y, -a0.y * b2.y);
    c1.z = fmaf(a2.z, b0.z, -a0.z * b2.z);
    c1.w = fmaf(a2.w, b0.w, -a0.w * b2.w);

    c2.x = fmaf(a0.x, b1.x, -a1.x * b0.x);
    c2.y = fmaf(a0.y, b1.y, -a1.y * b0.y);
    c2.z = fmaf(a0.z, b1.z, -a1.z * b0.z);
    c2.w = fmaf(a0.w, b1.w, -a1.w * b0.w);

    O[base]              = c0;
    O[base + CH_VEC]     = c1;
    O[base + 2 * CH_VEC] = c2;
}

extern "C" void kernel_launch(void* const* d_in, const int* in_sizes, int n_in,
                              void* d_out, int out_size)
{
    const float4* A = (const float4*)d_in[0];
    const float4* B = (const float4*)d_in[1];
    float4* O = (float4*)d_out;

    dim3 grid(CH_VEC / TPB, NBATCH, 1);   // (512, 16)
    cross_kernel<<<grid, TPB>>>(A, B, O);
}

// round 15
// speedup vs baseline: 1.0181x; 1.0181x over previous
#include <cuda_runtime.h>

// Cross product along dim=1 of (16, 3, 1024, 1024) fp32.
// FINAL champion (6 verification runs): one float4-triple per thread, plain
// LDG.128/STG.128, full 2D grid (spatial-x, batch-y), TPB=512.
// kernel 80.5-82.5us @ 6.8-6.93 TB/s (86-87.5% dram_active) — the HBM
// controller ceiling for a 2:1 read/write mix on 576 MiB minimum traffic.
//
// Mapped & falsified: TPB 256 (tied) / 1024 (worse); VPT=2 (83.4us);
// persistent grid (93.6us); __ldcs/__stcs (neutral/negative). Batch-major
// rasterization would multiply concurrent DRAM streams 9->144 (worse row
// locality). TMA/cp.async path-equivalent under the LTS cap. Converged.

static constexpr int CH_ELEMS  = 1024 * 1024;      // elements per channel plane
static constexpr int CH_VEC    = CH_ELEMS / 4;     // float4 vecs per channel plane
static constexpr int NBATCH    = 16;
static constexpr int TPB       = 512;

__global__ __launch_bounds__(TPB) void cross_kernel(
    const float4* __restrict__ A,
    const float4* __restrict__ B,
    float4* __restrict__ O)
{
    const int s = blockIdx.x * TPB + threadIdx.x;       // spatial vec index [0, CH_VEC)
    const int b = blockIdx.y;                           // batch
    const long base = (long)b * (3L * CH_VEC) + s;

    const float4 a0 = A[base];
    const float4 a1 = A[base + CH_VEC];
    const float4 a2 = A[base + 2 * CH_VEC];
    const float4 b0 = B[base];
    const float4 b1 = B[base + CH_VEC];
    const float4 b2 = B[base + 2 * CH_VEC];

    float4 c0, c1, c2;
    c0.x = fmaf(a1.x, b2.x, -a2.x * b1.x);
    c0.y = fmaf(a1.y, b2.y, -a2.y * b1.y);
    c0.z = fmaf(a1.z, b2.z, -a2.z * b1.z);
    c0.w = fmaf(a1.w, b2.w, -a2.w * b1.w);

    c1.x = fmaf(a2.x, b0.x, -a0.x * b2.x);
    c1.y = fmaf(a2.y, b0.y, -a0.y * b2.y);
    c1.z = fmaf(a2.z, b0.z, -a0.z * b2.z);
    c1.w = fmaf(a2.w, b0.w, -a0.w * b2.w);

    c2.x = fmaf(a0.x, b1.x, -a1.x * b0.x);
    c2.y = fmaf(a0.y, b1.y, -a1.y * b0.y);
    c2.z = fmaf(a0.z, b1.z, -a1.z * b0.z);
    c2.w = fmaf(a0.w, b1.w, -a1.w * b0.w);

    O[base]              = c0;
    O[base + CH_VEC]     = c1;
    O[base + 2 * CH_VEC] = c2;
}

extern "C" void kernel_launch(void* const* d_in, const int* in_sizes, int n_in,
                              void* d_out, int out_size)
{
    const float4* A = (const float4*)d_in[0];
    const float4* B = (const float4*)d_in[1];
    float4* O = (float4*)d_out;

    dim3 grid(CH_VEC / TPB, NBATCH, 1);   // (512, 16)
    cross_kernel<<<grid, TPB>>>(A, B, O);
}